// round 8
// baseline (speedup 1.0000x reference)
#include <cuda_runtime.h>

#define BB    4
#define NN    100000
#define MM    64
#define HM    32           // half of MM
#define TPB   256
#define BPI   185          // blocks per image; grid = 185*4 = 740 = 148 SMs * 5 CTAs (one wave)
#define CHUNK 541          // ceil(100000/185) = 541 = 2*256 + 29
#define REM   (CHUNK - 2 * TPB)   // 29

// Intersection + C = (S + Ap), bit-exact op order vs reference.
// Reference denom = (S + Ap) - inter; we defer the subtraction to the winner only.
// argmax(iou) == argmax(inter / (S+Ap)) since iou = r/(1-r) is monotone in r.
__device__ __forceinline__ void iou_ic(const float4 g, const float S,
                                       const float4 p, const float Ap,
                                       float& inter, float& C)
{
    const float ltx = fmaxf(g.x, p.x);
    const float lty = fmaxf(g.y, p.y);
    const float rbx = fminf(g.z, p.z);
    const float rby = fminf(g.w, p.w);
    const float wx  = fmaxf(__fsub_rn(rbx, ltx), 0.0f);
    const float wy  = fmaxf(__fsub_rn(rby, lty), 0.0f);
    inter = __fmul_rn(wx, wy);
    C     = __fadd_rn(S, Ap);
}

struct Best { float I, C; int i; };

// r_new > r_best  <=>  in * b.C > b.I * C   (C > 0); strict > keeps first max.
__device__ __forceinline__ void upd(Best& b, const float in, const float C, const int i)
{
    const bool t = __fmul_rn(in, b.C) > __fmul_rn(b.I, C);
    b.I = t ? in : b.I;
    b.C = t ? C  : b.C;
    b.i = t ? i  : b.i;
}

// Merge two half-range bests: upper half wins only on STRICT greater (first-max-wins).
__device__ __forceinline__ Best merge(const Best lo, const Best hi)
{
    const bool t = __fmul_rn(hi.I, lo.C) > __fmul_rn(lo.I, hi.C);
    Best w;
    w.I = t ? hi.I : lo.I;
    w.C = t ? hi.C : lo.C;
    w.i = t ? hi.i : lo.i;
    return w;
}

// Encode targets + decode deltas + write all three outputs for one proposal.
__device__ __forceinline__ void epilogue(const float4 p, const float4 d, const float4 mg,
                                         const int match, const int idx,
                                         float* __restrict__ out)
{
    const float aw = p.z - p.x;
    const float ah = p.w - p.y;
    const float ax = p.x + 0.5f * aw;
    const float ay = p.y + 0.5f * ah;
    const float rw = __fdividef(1.0f, aw);   // fast rcp: outputs only need 1e-3
    const float rh = __fdividef(1.0f, ah);

    const float gw = fmaxf(mg.z - mg.x, 1.0f);
    const float gh = fmaxf(mg.w - mg.y, 1.0f);
    const float gx = mg.x + 0.5f * gw;
    const float gy = mg.y + 0.5f * gh;

    float4 tgt;
    tgt.x = (gx - ax) * rw * 10.0f;   // / 0.1
    tgt.y = (gy - ay) * rh * 10.0f;
    tgt.z = __logf(gw * rw) * 5.0f;   // / 0.2
    tgt.w = __logf(gh * rh) * 5.0f;

    const float cx = ax + (d.x * 0.1f) * aw;
    const float cy = ay + (d.y * 0.1f) * ah;
    const float pw = __expf(d.z * 0.2f) * aw;
    const float ph = __expf(d.w * 0.2f) * ah;

    float4 dec;
    dec.x = cx - 0.5f * pw;
    dec.y = cy - 0.5f * ph;
    dec.z = cx + 0.5f * pw;
    dec.w = cy + 0.5f * ph;

    ((float4*)out)[idx] = dec;                       // decoded  [B,N,4]
    ((float4*)(out + 4 * BB * NN))[idx] = tgt;       // targets  [B,N,4]
    (out + 8 * BB * NN)[idx] = (float)match;         // matches  [B,N]
}

// Single-proposal matcher (2 half-streams) + epilogue; used by remainder lanes.
__device__ __forceinline__ void process_one(const float4* __restrict__ prop_b,
                                            const float4* __restrict__ del_b,
                                            const float4* __restrict__ sg,
                                            const float*  __restrict__ sS,
                                            const int n, const int bofs,
                                            float* __restrict__ out)
{
    const float4 p  = prop_b[n];
    const float  Ap = __fmul_rn(__fsub_rn(p.z, p.x), __fsub_rn(p.w, p.y));

    Best a, c;
    iou_ic(sg[0],  sS[0],  p, Ap, a.I, a.C); a.i = 0;
    iou_ic(sg[HM], sS[HM], p, Ap, c.I, c.C); c.i = HM;

    #pragma unroll 8
    for (int k = 1; k < HM; k++) {
        float in, Cc;
        iou_ic(sg[k], sS[k], p, Ap, in, Cc);
        upd(a, in, Cc, k);
        iou_ic(sg[HM + k], sS[HM + k], p, Ap, in, Cc);
        upd(c, in, Cc, HM + k);
    }

    const Best w = merge(a, c);
    const float denom = __fsub_rn(w.C, w.I);         // == reference's rounded denom
    const float iou   = __fdiv_rn(w.I, denom);       // exact -> threshold bit-faithful
    const int   m     = (iou < 0.5f) ? -1 : w.i;
    const float4 mg   = sg[(m < 0) ? 0 : w.i];
    epilogue(p, del_b[n], mg, m, bofs + n, out);
}

__global__ __launch_bounds__(TPB, 5)
void roihead_kernel(const float4* __restrict__ proposals,
                    const float4* __restrict__ gt,
                    const float4* __restrict__ deltas,
                    float* __restrict__ out)
{
    __shared__ float4 sg[MM];
    __shared__ float  sS[MM];

    const int b   = blockIdx.y;
    const int tid = threadIdx.x;

    if (tid < MM) {
        const float4 g = gt[b * MM + tid];
        sg[tid] = g;
        sS[tid] = __fmul_rn(__fsub_rn(g.z, g.x), __fsub_rn(g.w, g.y));
    }
    __syncthreads();

    const int base = blockIdx.x * CHUNK;
    const int bofs = b * NN;
    const float4* prop_b = proposals + bofs;
    const float4* del_b  = deltas    + bofs;

    // ---- pair phase: 2 proposals/thread x 2 gt-halves = 4 independent argmax streams.
    //      n0 never out of range (max 184*541 + 255 = 99799); n1 masked on last block.
    {
        const int  n0    = base + tid;
        const int  n1raw = base + TPB + tid;
        const bool v1    = (n1raw < NN);
        const int  n1    = v1 ? n1raw : n0;

        const float4 p0 = prop_b[n0];
        const float4 p1 = prop_b[n1];
        const float Ap0 = __fmul_rn(__fsub_rn(p0.z, p0.x), __fsub_rn(p0.w, p0.y));
        const float Ap1 = __fmul_rn(__fsub_rn(p1.z, p1.x), __fsub_rn(p1.w, p1.y));

        Best a0, c0, a1, c1;
        {
            const float4 gl = sg[0];  const float Sl = sS[0];
            const float4 gh = sg[HM]; const float Sh = sS[HM];
            iou_ic(gl, Sl, p0, Ap0, a0.I, a0.C); a0.i = 0;
            iou_ic(gl, Sl, p1, Ap1, a1.I, a1.C); a1.i = 0;
            iou_ic(gh, Sh, p0, Ap0, c0.I, c0.C); c0.i = HM;
            iou_ic(gh, Sh, p1, Ap1, c1.I, c1.C); c1.i = HM;
        }

        #pragma unroll 8
        for (int k = 1; k < HM; k++) {
            const float4 gl = sg[k];      const float Sl = sS[k];
            const float4 gh = sg[HM + k]; const float Sh = sS[HM + k];

            float in, Cc;
            iou_ic(gl, Sl, p0, Ap0, in, Cc); upd(a0, in, Cc, k);
            iou_ic(gl, Sl, p1, Ap1, in, Cc); upd(a1, in, Cc, k);
            iou_ic(gh, Sh, p0, Ap0, in, Cc); upd(c0, in, Cc, HM + k);
            iou_ic(gh, Sh, p1, Ap1, in, Cc); upd(c1, in, Cc, HM + k);
        }

        const Best w0 = merge(a0, c0);
        const Best w1 = merge(a1, c1);

        const float dn0  = __fsub_rn(w0.C, w0.I);    // reference-rounded denominators
        const float dn1  = __fsub_rn(w1.C, w1.I);
        const float iou0 = __fdiv_rn(w0.I, dn0);     // exact winner division
        const float iou1 = __fdiv_rn(w1.I, dn1);

        // FG_THRESH == BG_THRESH == 0.5 -> BETWEEN(-2) unreachable.
        const int m0 = (iou0 < 0.5f) ? -1 : w0.i;
        const int m1 = (iou1 < 0.5f) ? -1 : w1.i;

        const float4 mg0 = sg[(m0 < 0) ? 0 : w0.i];  // jnp.clip(matches, 0) gather
        const float4 mg1 = sg[(m1 < 0) ? 0 : w1.i];

        epilogue(p0, del_b[n0], mg0, m0, bofs + n0, out);
        if (v1)
            epilogue(p1, del_b[n1], mg1, m1, bofs + n1, out);
    }

    // ---- remainder phase: 29 lanes handle one more proposal each ----
    if (tid < REM) {
        const int n2 = base + 2 * TPB + tid;
        if (n2 < NN)
            process_one(prop_b, del_b, sg, sS, n2, bofs, out);
    }
}

extern "C" void kernel_launch(void* const* d_in, const int* in_sizes, int n_in,
                              void* d_out, int out_size)
{
    const float4* proposals = (const float4*)d_in[0];
    const float4* gt        = (const float4*)d_in[1];
    const float4* deltas    = (const float4*)d_in[2];
    float* out = (float*)d_out;

    dim3 grid(BPI, BB);
    roihead_kernel<<<grid, TPB>>>(proposals, gt, deltas, out);
}

// round 12
// speedup vs baseline: 1.0089x; 1.0089x over previous
#include <cuda_runtime.h>

#define BB    4
#define NN    100000
#define MM    64
#define TPB   256
#define BPI   185          // grid = 185*4 = 740 = 148 SMs * 5 CTAs (one wave)
#define CHUNK 541          // 541 = 2*256 + 29
#define REM   (CHUNK - 2 * TPB)   // 29
#define FULLMASK 0xFFFFFFFFu

// area with reference rounding
__device__ __forceinline__ float area_of(const float4 p) {
    return __fmul_rn(__fsub_rn(p.z, p.x), __fsub_rn(p.w, p.y));
}

// intersection with reference rounding (clamp-after-sub)
__device__ __forceinline__ float inter_of(const float4 g, const float4 p) {
    const float wx = fmaxf(__fsub_rn(fminf(g.z, p.z), fmaxf(g.x, p.x)), 0.0f);
    const float wy = fmaxf(__fsub_rn(fminf(g.w, p.w), fmaxf(g.y, p.y)), 0.0f);
    return __fmul_rn(wx, wy);
}

// decode predicted deltas -> decoded [B,N,4]
__device__ __forceinline__ void write_decoded(const float4 p, const float4 d,
                                              const int idx, float* __restrict__ out)
{
    const float aw = p.z - p.x, ah = p.w - p.y;
    const float ax = p.x + 0.5f * aw, ay = p.y + 0.5f * ah;
    const float cx = ax + (d.x * 0.1f) * aw;
    const float cy = ay + (d.y * 0.1f) * ah;
    const float pw = __expf(d.z * 0.2f) * aw;
    const float ph = __expf(d.w * 0.2f) * ah;
    float4 dec;
    dec.x = cx - 0.5f * pw; dec.y = cy - 0.5f * ph;
    dec.z = cx + 0.5f * pw; dec.w = cy + 0.5f * ph;
    ((float4*)out)[idx] = dec;
}

// encode targets vs matched gt + match value
__device__ __forceinline__ void write_targets(const float4 p, const float4 mg,
                                              const int m, const int idx,
                                              float* __restrict__ out)
{
    const float aw = p.z - p.x, ah = p.w - p.y;
    const float ax = p.x + 0.5f * aw, ay = p.y + 0.5f * ah;
    const float rw = __fdividef(1.0f, aw);   // outputs only need 1e-3
    const float rh = __fdividef(1.0f, ah);
    const float gw = fmaxf(mg.z - mg.x, 1.0f);
    const float gh = fmaxf(mg.w - mg.y, 1.0f);
    const float gx = mg.x + 0.5f * gw, gy = mg.y + 0.5f * gh;
    float4 tgt;
    tgt.x = (gx - ax) * rw * 10.0f;
    tgt.y = (gy - ay) * rh * 10.0f;
    tgt.z = __logf(gw * rw) * 5.0f;
    tgt.w = __logf(gh * rh) * 5.0f;
    ((float4*)(out + 4 * BB * NN))[idx] = tgt;
    (out + 8 * BB * NN)[idx] = (float)m;
}

// Warp-cooperative exact argmax for one qualifying proposal n (lane 'src' owns it).
// Each lane evaluates gt[lane] and gt[lane+32]; butterfly all-reduce with
// cross-product comparison (ratio order; exact ties -> smaller index = first-max).
__device__ __forceinline__ void resolve_one(const int n, const int lane, const int src,
                                            const float4* __restrict__ prop_b,
                                            const float4* __restrict__ sg,
                                            const float*  __restrict__ sNegS,
                                            const int bofs, float* __restrict__ out)
{
    const float4 P  = prop_b[n];          // L1 hit
    const float  Ap = area_of(P);

    const float4 gA = sg[lane];
    const float4 gB = sg[lane + 32];
    const float IA = inter_of(gA, P);
    const float IB = inter_of(gB, P);
    const float CA = __fadd_rn(-sNegS[lane],      Ap);   // S + Ap, reference rounding
    const float CB = __fadd_rn(-sNegS[lane + 32], Ap);

    // within-lane: upper index wins only on STRICT greater
    const bool up = __fmul_rn(IB, CA) > __fmul_rn(IA, CB);
    float I  = up ? IB : IA;
    float C  = up ? CB : CA;
    int   idx = up ? (lane + 32) : lane;

    #pragma unroll
    for (int off = 16; off > 0; off >>= 1) {
        const float Io = __shfl_xor_sync(FULLMASK, I,   off);
        const float Co = __shfl_xor_sync(FULLMASK, C,   off);
        const int   io = __shfl_xor_sync(FULLMASK, idx, off);
        const float x = __fmul_rn(Io, C);
        const float y = __fmul_rn(I, Co);
        const bool take = (x > y) || ((x == y) && (io < idx));
        I   = take ? Io : I;
        C   = take ? Co : C;
        idx = take ? io : idx;
    }

    if (lane == src) {
        const float denom = __fsub_rn(C, I);        // reference's rounded denom
        const float iou   = __fdiv_rn(I, denom);    // exact -> threshold bit-faithful
        const int   m     = (iou < 0.5f) ? -1 : idx;
        const float4 mg   = sg[(m < 0) ? 0 : idx];
        write_targets(P, mg, m, bofs + n, out);
    }
}

// Exact per-thread path for remainder lanes (29 per block): full argmax scan.
__device__ __forceinline__ void process_one(const float4* __restrict__ prop_b,
                                            const float4* __restrict__ del_b,
                                            const float4* __restrict__ sg,
                                            const float*  __restrict__ sNegS,
                                            const int n, const int bofs,
                                            float* __restrict__ out)
{
    const float4 p  = prop_b[n];
    const float  Ap = area_of(p);

    float bI = inter_of(sg[0], p);
    float bC = __fadd_rn(-sNegS[0], Ap);
    int   bi = 0;

    #pragma unroll 8
    for (int i = 1; i < MM; i++) {
        const float in = inter_of(sg[i], p);
        const float C  = __fadd_rn(-sNegS[i], Ap);
        if (__fmul_rn(in, bC) > __fmul_rn(bI, C)) { bI = in; bC = C; bi = i; }
    }

    const float denom = __fsub_rn(bC, bI);
    const float iou   = __fdiv_rn(bI, denom);
    const int   m     = (iou < 0.5f) ? -1 : bi;
    const float4 mg   = sg[(m < 0) ? 0 : bi];
    write_decoded(p, del_b[n], bofs + n, out);
    write_targets(p, mg, m, bofs + n, out);
}

__global__ __launch_bounds__(TPB, 5)
void roihead_kernel(const float4* __restrict__ proposals,
                    const float4* __restrict__ gt,
                    const float4* __restrict__ deltas,
                    float* __restrict__ out)
{
    __shared__ float4 sg[MM];
    __shared__ float  sNegS[MM];      // -area(gt_i): FFMA third operand

    const int b    = blockIdx.y;
    const int tid  = threadIdx.x;
    const int lane = tid & 31;
    const int wid  = tid >> 5;

    if (tid < MM) {
        const float4 g = gt[b * MM + tid];
        sg[tid]    = g;
        sNegS[tid] = -area_of(g);
    }
    __syncthreads();

    const int base = blockIdx.x * CHUNK;
    const int bofs = b * NN;
    const float4* prop_b = proposals + bofs;
    const float4* del_b  = deltas    + bofs;

    // ---- Phase A: qualification scan (no argmax state). 2 proposals/thread.
    //      u_i = fma(inter_i, 3, -S_i); qualifier iff max_i u_i >= Ap
    //      (iou >= 0.5  <=>  3*inter >= S + Ap, up to 1-ulp boundary noise).
    const int  n0    = base + tid;                // always < NN (max 99799)
    const int  n1raw = base + TPB + tid;
    const bool v1    = (n1raw < NN);
    const int  n1    = v1 ? n1raw : n0;

    const float4 p0 = prop_b[n0];
    const float4 p1 = prop_b[n1];
    const float Ap0 = area_of(p0);
    const float Ap1 = area_of(p1);

    float mu0 = -3.4e38f, mu1 = -3.4e38f;
    #pragma unroll 8
    for (int i = 0; i < MM; i++) {
        const float4 g  = sg[i];
        const float  ns = sNegS[i];
        mu0 = fmaxf(mu0, __fmaf_rn(inter_of(g, p0), 3.0f, ns));
        mu1 = fmaxf(mu1, __fmaf_rn(inter_of(g, p1), 3.0f, ns));
    }
    const bool q0 = (mu0 >= Ap0);
    const bool q1 = v1 && (mu1 >= Ap1);

    // decoded always; default targets (match=-1, gather gt[0]) for non-qualifiers
    write_decoded(p0, del_b[n0], bofs + n0, out);
    if (!q0) write_targets(p0, sg[0], -1, bofs + n0, out);
    if (v1) {
        write_decoded(p1, del_b[n1], bofs + n1, out);
        if (!q1) write_targets(p1, sg[0], -1, bofs + n1, out);
    }

    // ---- Phase B: warp-cooperative exact argmax for the rare qualifiers ----
    unsigned m0 = __ballot_sync(FULLMASK, q0);
    unsigned m1 = __ballot_sync(FULLMASK, q1);
    const int warp_n0 = base + (wid << 5);        // n of lane 0, stream 0

    while (m0) {
        const int s = __ffs(m0) - 1; m0 &= m0 - 1;
        resolve_one(warp_n0 + s, lane, s, prop_b, sg, sNegS, bofs, out);
    }
    while (m1) {
        const int s = __ffs(m1) - 1; m1 &= m1 - 1;
        resolve_one(warp_n0 + TPB + s, lane, s, prop_b, sg, sNegS, bofs, out);
    }

    // ---- remainder: 29 lanes handle one more proposal each (exact path) ----
    if (tid < REM) {
        const int n2 = base + 2 * TPB + tid;
        if (n2 < NN)
            process_one(prop_b, del_b, sg, sNegS, n2, bofs, out);
    }
}

extern "C" void kernel_launch(void* const* d_in, const int* in_sizes, int n_in,
                              void* d_out, int out_size)
{
    const float4* proposals = (const float4*)d_in[0];
    const float4* gt        = (const float4*)d_in[1];
    const float4* deltas    = (const float4*)d_in[2];
    float* out = (float*)d_out;

    dim3 grid(BPI, BB);
    roihead_kernel<<<grid, TPB>>>(proposals, gt, deltas, out);
}